// round 4
// baseline (speedup 1.0000x reference)
#include <cuda_runtime.h>

#define EMBED 16
// tokens = BATCH * SEQ = 128 * 8192 = 1048576

// Register/occupancy operating point:
//   R2: (256,8) -> 32 regs -> spills -> 1.8GB local traffic -> 356us
//   R3: unbounded -> 255 regs -> occ 11% -> latency-bound, HBM 1.5TB/s -> 67us
//   R4: (256,4) -> 64-reg cap (live set ~45, no spills), occ 50%,
//       1024 thr/SM * 4 in-flight 16B loads = 64KB/SM in flight >> ~15KB needed
//       to sustain full HBM bandwidth.
__global__ __launch_bounds__(256, 4)
void mhaq_kernel(const float* __restrict__ x,
                 const float* __restrict__ theta,
                 const float* __restrict__ w_out,
                 float* __restrict__ y,
                 int n_tokens)
{
    __shared__ float s_theta[EMBED];
    __shared__ float s_w[EMBED * EMBED];   // w[o][e] row-major

    int tid = threadIdx.x;
    if (tid < EMBED) s_theta[tid] = theta[tid];
    if (tid < EMBED * EMBED) s_w[tid] = w_out[tid];
    __syncthreads();

    int stride = gridDim.x * blockDim.x;

    for (int token = blockIdx.x * blockDim.x + tid; token < n_tokens; token += stride) {
        const float4* xv = reinterpret_cast<const float4*>(x) + (size_t)token * 4;
        float4*       yv = reinterpret_cast<float4*>(y) + (size_t)token * 4;

        // 4 independent 128-bit loads -> MLP=4, warp covers 2048B contiguous
        float4 x0 = xv[0];
        float4 x1 = xv[1];
        float4 x2 = xv[2];
        float4 x3 = xv[3];

        float z[EMBED];
        z[ 0] = __cosf(x0.x + s_theta[ 0]);
        z[ 1] = __cosf(x0.y + s_theta[ 1]);
        z[ 2] = __cosf(x0.z + s_theta[ 2]);
        z[ 3] = __cosf(x0.w + s_theta[ 3]);
        z[ 4] = __cosf(x1.x + s_theta[ 4]);
        z[ 5] = __cosf(x1.y + s_theta[ 5]);
        z[ 6] = __cosf(x1.z + s_theta[ 6]);
        z[ 7] = __cosf(x1.w + s_theta[ 7]);
        z[ 8] = __cosf(x2.x + s_theta[ 8]);
        z[ 9] = __cosf(x2.y + s_theta[ 9]);
        z[10] = __cosf(x2.z + s_theta[10]);
        z[11] = __cosf(x2.w + s_theta[11]);
        z[12] = __cosf(x3.x + s_theta[12]);
        z[13] = __cosf(x3.y + s_theta[13]);
        z[14] = __cosf(x3.z + s_theta[14]);
        z[15] = __cosf(x3.w + s_theta[15]);

        float acc[EMBED];
        #pragma unroll
        for (int o = 0; o < EMBED; o++) acc[o] = z[0] * s_w[o * EMBED];

        #pragma unroll
        for (int e = 1; e < EMBED; e++) {
            float ze = z[e];
            #pragma unroll
            for (int o = 0; o < EMBED; o++) {
                acc[o] = fmaf(ze, s_w[o * EMBED + e], acc[o]);
            }
        }

        yv[0] = make_float4(acc[ 0], acc[ 1], acc[ 2], acc[ 3]);
        yv[1] = make_float4(acc[ 4], acc[ 5], acc[ 6], acc[ 7]);
        yv[2] = make_float4(acc[ 8], acc[ 9], acc[10], acc[11]);
        yv[3] = make_float4(acc[12], acc[13], acc[14], acc[15]);
    }
}

extern "C" void kernel_launch(void* const* d_in, const int* in_sizes, int n_in,
                              void* d_out, int out_size)
{
    const float* x     = (const float*)d_in[0];   // [B, S, E] = [128, 8192, 16]
    const float* theta = (const float*)d_in[1];   // [E]
    const float* w_out = (const float*)d_in[2];   // [E, E] (o, e)
    float* y           = (float*)d_out;           // [B, S, E]

    int n_tokens = in_sizes[0] / EMBED;           // 1048576
    int threads = 256;
    int blocks = (n_tokens + threads - 1) / threads;
    mhaq_kernel<<<blocks, threads>>>(x, theta, w_out, y, n_tokens);
}

// round 5
// speedup vs baseline: 5.2543x; 5.2543x over previous
#include <cuda_runtime.h>

#define EMBED 16
// tokens = BATCH * SEQ = 128 * 8192 = 1048576 (divides 256 exactly)

// Operating-point history:
//   R2: cap 32  -> spills -> 1.8GB DRAM -> 356us
//   R3: cap 255 -> no spills, 1 block/SM (occ 12.5%) -> latency-bound -> 67us
//   R4: cap 64  -> STILL spills (~1.0GB DRAM) -> 207us
//   R5: restructured body (cos fused into FMA loop, no grid-stride loop) to cut
//       peak live regs to ~45; cap 85 via (256,3) -> no spills + occ 37.5%.
__global__ __launch_bounds__(256, 3)
void mhaq_kernel(const float* __restrict__ x,
                 const float* __restrict__ theta,
                 const float* __restrict__ w_out,
                 float* __restrict__ y)
{
    __shared__ float s_theta[EMBED];
    __shared__ float s_w[EMBED * EMBED];   // w[o][e] row-major

    int tid = threadIdx.x;
    if (tid < EMBED) s_theta[tid] = theta[tid];
    if (tid < EMBED * EMBED) s_w[tid] = w_out[tid];
    __syncthreads();

    int token = blockIdx.x * blockDim.x + tid;   // grid sized exactly

    const float4* xv = reinterpret_cast<const float4*>(x) + (size_t)token * 4;
    float4*       yv = reinterpret_cast<float4*>(y) + (size_t)token * 4;

    // 4 independent 128-bit loads issued up front -> MLP=4, coalesced 2048B/warp
    float4 a = xv[0];
    float4 b = xv[1];
    float4 c = xv[2];
    float4 d = xv[3];

    float xr[EMBED] = { a.x, a.y, a.z, a.w,
                        b.x, b.y, b.z, b.w,
                        c.x, c.y, c.z, c.w,
                        d.x, d.y, d.z, d.w };

    float acc[EMBED];

    // e = 0: initialize accumulators (avoids zero-init pass)
    {
        float z0 = __cosf(xr[0] + s_theta[0]);
        #pragma unroll
        for (int o = 0; o < EMBED; o++) acc[o] = z0 * s_w[o * EMBED];
    }

    // cos fused into the accumulation loop: only ONE z live at a time.
    // xr[e] dies as acc grows -> peak live ~ 16 + 16 + temps.
    #pragma unroll
    for (int e = 1; e < EMBED; e++) {
        float ze = __cosf(xr[e] + s_theta[e]);
        #pragma unroll
        for (int o = 0; o < EMBED; o++) {
            acc[o] = fmaf(ze, s_w[o * EMBED + e], acc[o]);  // smem broadcast
        }
    }

    yv[0] = make_float4(acc[ 0], acc[ 1], acc[ 2], acc[ 3]);
    yv[1] = make_float4(acc[ 4], acc[ 5], acc[ 6], acc[ 7]);
    yv[2] = make_float4(acc[ 8], acc[ 9], acc[10], acc[11]);
    yv[3] = make_float4(acc[12], acc[13], acc[14], acc[15]);
}

extern "C" void kernel_launch(void* const* d_in, const int* in_sizes, int n_in,
                              void* d_out, int out_size)
{
    const float* x     = (const float*)d_in[0];   // [B, S, E] = [128, 8192, 16]
    const float* theta = (const float*)d_in[1];   // [E]
    const float* w_out = (const float*)d_in[2];   // [E, E] (o, e)
    float* y           = (float*)d_out;           // [B, S, E]

    int n_tokens = in_sizes[0] / EMBED;           // 1048576, multiple of 256
    int threads = 256;
    int blocks = n_tokens / threads;              // 4096, exact
    mhaq_kernel<<<blocks, threads>>>(x, theta, w_out, y);
}